// round 9
// baseline (speedup 1.0000x reference)
#include <cuda_runtime.h>
#include <cstdint>

#define DIM 256
#define NQ  8192
#define NE  8192
#define NW  64               // 64 int32 words per row (256 int8)
#define ZQ_ELEMS (NQ * DIM)
#define NTILE 64             // code tiles of 128
#define BNPW 132             // padded Bs row stride (ints)
#define CAND_CAP 64

#define A_SZ   (64 * 64 * 4)                 // 16384
#define B_SZ   (NW * BNPW * 4)               // 33792
#define C_SZ   (64 * CAND_CAP * 4)           // 16384
#define SMEM_SC (A_SZ + 2 * B_SZ + C_SZ)     // 100352

// ---------------- device scratch (device-side references only) ----------------
__device__ float g_znorm[NQ * DIM];
__device__ float g_znorm2[NQ];
__device__ float g_zinv[NQ];
__device__ float g_zdel[NQ];
__device__ int   g_qz[NQ * NW];
__device__ float g_enorm[NE * DIM];
__device__ float g_enorm2[NE];
__device__ float g_einv[NE];
__device__ float g_edel[NE];
__device__ int   g_qe[NE * NW];
__device__ float g_demax[1];
__device__ int   g_cand[NQ * CAND_CAP];
__device__ int   g_cnt[NQ];
__device__ float g_partial[NQ];

// ---------------- L2 normalize + int8 quantize ----------------
__global__ void norm_quant(const float* __restrict__ in, int rows, int is_code) {
    int row  = (blockIdx.x * blockDim.x + threadIdx.x) >> 5;
    int lane = threadIdx.x & 31;
    if (row >= rows) return;
    float* __restrict__ outv = is_code ? g_enorm : g_znorm;
    const float4* src = (const float4*)(in + (size_t)row * DIM);
    float4 v0 = src[lane];
    float4 v1 = src[lane + 32];
    float s = v0.x*v0.x + v0.y*v0.y + v0.z*v0.z + v0.w*v0.w
            + v1.x*v1.x + v1.y*v1.y + v1.z*v1.z + v1.w*v1.w;
    #pragma unroll
    for (int off = 16; off; off >>= 1) s += __shfl_xor_sync(0xffffffffu, s, off);
    float inv = 1.0f / fmaxf(sqrtf(s), 1e-12f);
    v0.x *= inv; v0.y *= inv; v0.z *= inv; v0.w *= inv;
    v1.x *= inv; v1.y *= inv; v1.z *= inv; v1.w *= inv;
    float4* dst = (float4*)(outv + (size_t)row * DIM);
    dst[lane]      = v0;
    dst[lane + 32] = v1;

    float vals[8] = {v0.x, v0.y, v0.z, v0.w, v1.x, v1.y, v1.z, v1.w};
    float s2 = 0.f;
    #pragma unroll
    for (int j = 0; j < 8; j++) s2 += vals[j] * vals[j];
    #pragma unroll
    for (int off = 16; off; off >>= 1) s2 += __shfl_xor_sync(0xffffffffu, s2, off);

    float mx = 0.f;
    #pragma unroll
    for (int j = 0; j < 8; j++) mx = fmaxf(mx, fabsf(vals[j]));
    #pragma unroll
    for (int off = 16; off; off >>= 1) mx = fmaxf(mx, __shfl_xor_sync(0xffffffffu, mx, off));
    float sc    = 127.0f / mx;
    float scinv = mx / 127.0f;

    int h[8];
    float dsum = 0.f;
    #pragma unroll
    for (int j = 0; j < 8; j++) {
        h[j] = (int)rintf(vals[j] * sc);
        float e = vals[j] - (float)h[j] * scinv;
        dsum += e * e;
    }
    #pragma unroll
    for (int off = 16; off; off >>= 1) dsum += __shfl_xor_sync(0xffffffffu, dsum, off);

    int w0 = (h[0] & 0xFF) | ((h[1] & 0xFF) << 8) | ((h[2] & 0xFF) << 16) | (h[3] << 24);
    int w1 = (h[4] & 0xFF) | ((h[5] & 0xFF) << 8) | ((h[6] & 0xFF) << 16) | (h[7] << 24);
    int* qp = is_code ? g_qe : g_qz;
    qp[(size_t)row * NW + lane]      = w0;
    qp[(size_t)row * NW + 32 + lane] = w1;
    if (lane == 0) {
        if (is_code) { g_enorm2[row] = s2; g_einv[row] = scinv; g_edel[row] = sqrtf(dsum); }
        else         { g_znorm2[row] = s2; g_zinv[row] = scinv; g_zdel[row] = sqrtf(dsum); }
    }
}

__global__ void demax_reduce() {
    __shared__ float sh[256];
    int tid = threadIdx.x;
    float m = 0.f;
    for (int i = tid; i < NE; i += 256) m = fmaxf(m, g_edel[i]);
    sh[tid] = m;
    __syncthreads();
    for (int off = 128; off; off >>= 1) {
        if (tid < off) sh[tid] = fmaxf(sh[tid], sh[tid + off]);
        __syncthreads();
    }
    if (tid == 0) g_demax[0] = sh[0];
}

// ---------------- dp4a screen with fused candidate collection ----------------
// 128 blocks x 256 thr; 64 rows/block; all 8192 codes in 64 tiles of 128.
// Per-warp rows ty*8..+7 (exclusive): register rowbest via shfl-min; candidates
// with key <= rowbest + margin pushed ballot-compacted into smem lists.
__global__ __launch_bounds__(256, 2)
void screen() {
    extern __shared__ char smem[];
    int* As    = (int*)smem;                       // [NW][64] transposed
    int* Bs    = (int*)(smem + A_SZ);              // [2][NW][BNPW] transposed
    int* scand = (int*)(smem + A_SZ + 2 * B_SZ);   // [64][CAND_CAP]

    const int tid = threadIdx.x;
    const int tx  = tid & 31;
    const int ty  = tid >> 5;
    const int qbase = blockIdx.x * 64;

    // ---- A load, transposed ----
    {
        int row = tid >> 2, p = tid & 3;
        #pragma unroll
        for (int j = 0; j < 4; j++) {
            int w = p * 16 + j * 4;
            int4 v = *(const int4*)&g_qz[(size_t)(qbase + row) * NW + w];
            As[(w + 0) * 64 + row] = v.x;
            As[(w + 1) * 64 + row] = v.y;
            As[(w + 2) * 64 + row] = v.z;
            As[(w + 3) * 64 + row] = v.w;
        }
    }

    // per-row scalars
    float z2s[8], qiv[8], marg[8], rowbest[8];
    int   cnt[8];
    {
        float D = g_demax[0];
        #pragma unroll
        for (int i = 0; i < 8; i++) {
            int r = qbase + ty * 8 + i;
            z2s[i] = g_znorm2[r];
            qiv[i] = g_zinv[r];
            float dq = g_zdel[r];
            marg[i] = 4.0f * (dq + D + 3.0f * dq * D) + 0.01f;
            rowbest[i] = 3.4e38f;
            cnt[i] = 0;
        }
    }

    // ---- prologue: tile 0 into buffer 0 ----
    const int c  = tid >> 1;
    const int hf = tid & 1;
    {
        #pragma unroll
        for (int j = 0; j < 8; j++) {
            int w = hf * 32 + j * 4;
            int4 v = *(const int4*)&g_qe[(size_t)c * NW + w];
            Bs[(w + 0) * BNPW + c] = v.x;
            Bs[(w + 1) * BNPW + c] = v.y;
            Bs[(w + 2) * BNPW + c] = v.z;
            Bs[(w + 3) * BNPW + c] = v.w;
        }
    }
    __syncthreads();

    int acc[8][4];
    int4 br[4];

    #pragma unroll 1
    for (int t = 0; t < NTILE; t++) {
        const int buf = t & 1;
        const int pre = (t + 1 < NTILE);
        #pragma unroll
        for (int i = 0; i < 8; i++) {
            acc[i][0] = 0; acc[i][1] = 0; acc[i][2] = 0; acc[i][3] = 0;
        }
        if (pre) {
            #pragma unroll
            for (int j = 0; j < 4; j++)
                br[j] = *(const int4*)&g_qe[(size_t)((t + 1) * 128 + c) * NW + hf * 32 + j * 4];
        }

        const int* B = Bs + buf * (NW * BNPW);
        #pragma unroll 8
        for (int kw = 0; kw < 32; kw++) {
            int4 a0 = *(const int4*)&As[kw * 64 + ty * 8];
            int4 a1 = *(const int4*)&As[kw * 64 + ty * 8 + 4];
            int4 b  = *(const int4*)&B[kw * BNPW + tx * 4];
            acc[0][0] = __dp4a(a0.x, b.x, acc[0][0]); acc[0][1] = __dp4a(a0.x, b.y, acc[0][1]);
            acc[0][2] = __dp4a(a0.x, b.z, acc[0][2]); acc[0][3] = __dp4a(a0.x, b.w, acc[0][3]);
            acc[1][0] = __dp4a(a0.y, b.x, acc[1][0]); acc[1][1] = __dp4a(a0.y, b.y, acc[1][1]);
            acc[1][2] = __dp4a(a0.y, b.z, acc[1][2]); acc[1][3] = __dp4a(a0.y, b.w, acc[1][3]);
            acc[2][0] = __dp4a(a0.z, b.x, acc[2][0]); acc[2][1] = __dp4a(a0.z, b.y, acc[2][1]);
            acc[2][2] = __dp4a(a0.z, b.z, acc[2][2]); acc[2][3] = __dp4a(a0.z, b.w, acc[2][3]);
            acc[3][0] = __dp4a(a0.w, b.x, acc[3][0]); acc[3][1] = __dp4a(a0.w, b.y, acc[3][1]);
            acc[3][2] = __dp4a(a0.w, b.z, acc[3][2]); acc[3][3] = __dp4a(a0.w, b.w, acc[3][3]);
            acc[4][0] = __dp4a(a1.x, b.x, acc[4][0]); acc[4][1] = __dp4a(a1.x, b.y, acc[4][1]);
            acc[4][2] = __dp4a(a1.x, b.z, acc[4][2]); acc[4][3] = __dp4a(a1.x, b.w, acc[4][3]);
            acc[5][0] = __dp4a(a1.y, b.x, acc[5][0]); acc[5][1] = __dp4a(a1.y, b.y, acc[5][1]);
            acc[5][2] = __dp4a(a1.y, b.z, acc[5][2]); acc[5][3] = __dp4a(a1.y, b.w, acc[5][3]);
            acc[6][0] = __dp4a(a1.z, b.x, acc[6][0]); acc[6][1] = __dp4a(a1.z, b.y, acc[6][1]);
            acc[6][2] = __dp4a(a1.z, b.z, acc[6][2]); acc[6][3] = __dp4a(a1.z, b.w, acc[6][3]);
            acc[7][0] = __dp4a(a1.w, b.x, acc[7][0]); acc[7][1] = __dp4a(a1.w, b.y, acc[7][1]);
            acc[7][2] = __dp4a(a1.w, b.z, acc[7][2]); acc[7][3] = __dp4a(a1.w, b.w, acc[7][3]);
        }
        if (pre) {
            int* Bn = Bs + ((t + 1) & 1) * (NW * BNPW);
            #pragma unroll
            for (int j = 0; j < 4; j++) {
                int w = hf * 32 + j * 4;
                Bn[(w + 0) * BNPW + c] = br[j].x;
                Bn[(w + 1) * BNPW + c] = br[j].y;
                Bn[(w + 2) * BNPW + c] = br[j].z;
                Bn[(w + 3) * BNPW + c] = br[j].w;
            }
            #pragma unroll
            for (int j = 0; j < 4; j++)
                br[j] = *(const int4*)&g_qe[(size_t)((t + 1) * 128 + c) * NW + hf * 32 + 16 + j * 4];
        }
        #pragma unroll 8
        for (int kw = 32; kw < 64; kw++) {
            int4 a0 = *(const int4*)&As[kw * 64 + ty * 8];
            int4 a1 = *(const int4*)&As[kw * 64 + ty * 8 + 4];
            int4 b  = *(const int4*)&B[kw * BNPW + tx * 4];
            acc[0][0] = __dp4a(a0.x, b.x, acc[0][0]); acc[0][1] = __dp4a(a0.x, b.y, acc[0][1]);
            acc[0][2] = __dp4a(a0.x, b.z, acc[0][2]); acc[0][3] = __dp4a(a0.x, b.w, acc[0][3]);
            acc[1][0] = __dp4a(a0.y, b.x, acc[1][0]); acc[1][1] = __dp4a(a0.y, b.y, acc[1][1]);
            acc[1][2] = __dp4a(a0.y, b.z, acc[1][2]); acc[1][3] = __dp4a(a0.y, b.w, acc[1][3]);
            acc[2][0] = __dp4a(a0.z, b.x, acc[2][0]); acc[2][1] = __dp4a(a0.z, b.y, acc[2][1]);
            acc[2][2] = __dp4a(a0.z, b.z, acc[2][2]); acc[2][3] = __dp4a(a0.z, b.w, acc[2][3]);
            acc[3][0] = __dp4a(a0.w, b.x, acc[3][0]); acc[3][1] = __dp4a(a0.w, b.y, acc[3][1]);
            acc[3][2] = __dp4a(a0.w, b.z, acc[3][2]); acc[3][3] = __dp4a(a0.w, b.w, acc[3][3]);
            acc[4][0] = __dp4a(a1.x, b.x, acc[4][0]); acc[4][1] = __dp4a(a1.x, b.y, acc[4][1]);
            acc[4][2] = __dp4a(a1.x, b.z, acc[4][2]); acc[4][3] = __dp4a(a1.x, b.w, acc[4][3]);
            acc[5][0] = __dp4a(a1.y, b.x, acc[5][0]); acc[5][1] = __dp4a(a1.y, b.y, acc[5][1]);
            acc[5][2] = __dp4a(a1.y, b.z, acc[5][2]); acc[5][3] = __dp4a(a1.y, b.w, acc[5][3]);
            acc[6][0] = __dp4a(a1.z, b.x, acc[6][0]); acc[6][1] = __dp4a(a1.z, b.y, acc[6][1]);
            acc[6][2] = __dp4a(a1.z, b.z, acc[6][2]); acc[6][3] = __dp4a(a1.z, b.w, acc[6][3]);
            acc[7][0] = __dp4a(a1.w, b.x, acc[7][0]); acc[7][1] = __dp4a(a1.w, b.y, acc[7][1]);
            acc[7][2] = __dp4a(a1.w, b.z, acc[7][2]); acc[7][3] = __dp4a(a1.w, b.w, acc[7][3]);
        }
        if (pre) {
            int* Bn = Bs + ((t + 1) & 1) * (NW * BNPW);
            #pragma unroll
            for (int j = 0; j < 4; j++) {
                int w = hf * 32 + 16 + j * 4;
                Bn[(w + 0) * BNPW + c] = br[j].x;
                Bn[(w + 1) * BNPW + c] = br[j].y;
                Bn[(w + 2) * BNPW + c] = br[j].z;
                Bn[(w + 3) * BNPW + c] = br[j].w;
            }
        }
        __syncthreads();

        // ---- epilogue: keys, rowbest, candidate pushes ----
        int colb = t * 128 + tx * 4;
        float4 e2  = *(const float4*)&g_enorm2[colb];
        float4 civ = *(const float4*)&g_einv[colb];
        #pragma unroll
        for (int i = 0; i < 8; i++) {
            float sc = qiv[i];
            float k0 = z2s[i] + e2.x - 2.0f * ((float)acc[i][0] * (sc * civ.x));
            float k1 = z2s[i] + e2.y - 2.0f * ((float)acc[i][1] * (sc * civ.y));
            float k2 = z2s[i] + e2.z - 2.0f * ((float)acc[i][2] * (sc * civ.z));
            float k3 = z2s[i] + e2.w - 2.0f * ((float)acc[i][3] * (sc * civ.w));
            float m = fminf(fminf(k0, k1), fminf(k2, k3));
            #pragma unroll
            for (int off = 16; off; off >>= 1) m = fminf(m, __shfl_xor_sync(0xffffffffu, m, off));
            rowbest[i] = fminf(rowbest[i], m);
            float thr = rowbest[i] + marg[i];
            unsigned lt = (1u << tx) - 1u;
            int* lst = &scand[(ty * 8 + i) * CAND_CAP];
            unsigned b0 = __ballot_sync(0xffffffffu, k0 <= thr);
            if (k0 <= thr) { int p = cnt[i] + __popc(b0 & lt); if (p < CAND_CAP) lst[p] = colb; }
            cnt[i] += __popc(b0);
            unsigned b1 = __ballot_sync(0xffffffffu, k1 <= thr);
            if (k1 <= thr) { int p = cnt[i] + __popc(b1 & lt); if (p < CAND_CAP) lst[p] = colb + 1; }
            cnt[i] += __popc(b1);
            unsigned b2 = __ballot_sync(0xffffffffu, k2 <= thr);
            if (k2 <= thr) { int p = cnt[i] + __popc(b2 & lt); if (p < CAND_CAP) lst[p] = colb + 2; }
            cnt[i] += __popc(b2);
            unsigned b3 = __ballot_sync(0xffffffffu, k3 <= thr);
            if (k3 <= thr) { int p = cnt[i] + __popc(b3 & lt); if (p < CAND_CAP) lst[p] = colb + 3; }
            cnt[i] += __popc(b3);
        }
    }

    // ---- write candidate lists + counts ----
    __syncwarp();
    #pragma unroll
    for (int i = 0; i < 8; i++) {
        int rowg = qbase + ty * 8 + i;
        int n = cnt[i];
        if (tx == 0) g_cnt[rowg] = n;
        int lim = (n < CAND_CAP) ? n : CAND_CAP;
        for (int j = tx; j < lim; j += 32)
            g_cand[rowg * CAND_CAP + j] = scand[(ty * 8 + i) * CAND_CAP + j];
    }
}

// ---------------- fused exact rescoring + gather + loss partial ----------------
__global__ void rescore_gather(float* __restrict__ zq_out, float* __restrict__ idxf_out,
                               int write_zq) {
    __shared__ unsigned long long wmin[8];
    __shared__ float wls[2];
    __shared__ int s_e;
    int row = blockIdx.x;
    int tid = threadIdx.x;
    int lane = tid & 31;
    int w = tid >> 5;
    int cnt = g_cnt[row];
    float z2 = g_znorm2[row];
    const float* zr = &g_znorm[(size_t)row * DIM];

    unsigned long long lmin = 0xFFFFFFFFFFFFFFFFull;

    if (cnt > 0 && cnt <= CAND_CAP) {
        const float4* zv = (const float4*)zr;
        float4 b0 = zv[lane], b1 = zv[lane + 32];
        for (int i = w; i < cnt; i += 8) {
            int code = g_cand[row * CAND_CAP + i];
            const float4* ev = (const float4*)&g_enorm[(size_t)code * DIM];
            float4 a0 = ev[lane], a1 = ev[lane + 32];
            float d = a0.x*b0.x + a0.y*b0.y + a0.z*b0.z + a0.w*b0.w
                    + a1.x*b1.x + a1.y*b1.y + a1.z*b1.z + a1.w*b1.w;
            #pragma unroll
            for (int off = 16; off; off >>= 1) d += __shfl_xor_sync(0xffffffffu, d, off);
            float key = z2 + g_enorm2[code] - 2.0f * d;
            unsigned long long p = ((unsigned long long)__float_as_uint(key) << 32) | (unsigned)code;
            lmin = min(lmin, p);
        }
    } else {
        // overflow safety: exact full scan (codes L2-resident)
        for (int n = tid; n < NE; n += 256) {
            const float* er = &g_enorm[(size_t)n * DIM];
            float dot = 0.f;
            #pragma unroll 8
            for (int d2 = 0; d2 < DIM; d2++) dot = fmaf(zr[d2], er[d2], dot);
            float key = z2 + g_enorm2[n] - 2.0f * dot;
            unsigned long long p = ((unsigned long long)__float_as_uint(key) << 32) | (unsigned)n;
            lmin = min(lmin, p);
        }
    }
    #pragma unroll
    for (int off = 16; off; off >>= 1) {
        unsigned long long o = __shfl_xor_sync(0xffffffffu, lmin, off);
        lmin = min(lmin, o);
    }
    if (lane == 0) wmin[w] = lmin;
    __syncthreads();
    if (tid == 0) {
        unsigned long long m = wmin[0];
        #pragma unroll
        for (int i = 1; i < 8; i++) m = min(m, wmin[i]);
        s_e = (int)(m & 0xFFFFFFFFull);
    }
    __syncthreads();

    int e = s_e & (NE - 1);
    if (tid < 64) {
        float4 a = ((const float4*)&g_enorm[(size_t)e * DIM])[tid];
        float4 b = ((const float4*)&g_znorm[(size_t)row * DIM])[tid];
        if (write_zq) ((float4*)&zq_out[(size_t)row * DIM])[tid] = a;
        float dx, s = 0.f;
        dx = a.x - b.x; s += dx * dx;
        dx = a.y - b.y; s += dx * dx;
        dx = a.z - b.z; s += dx * dx;
        dx = a.w - b.w; s += dx * dx;
        #pragma unroll
        for (int off = 16; off; off >>= 1) s += __shfl_xor_sync(0xffffffffu, s, off);
        if (lane == 0) wls[tid >> 5] = s;
    }
    __syncthreads();
    if (tid == 0) {
        g_partial[row] = wls[0] + wls[1];
        if (idxf_out) idxf_out[row] = (float)e;
    }
}

__global__ void finalize_loss(float* __restrict__ loss_out) {
    __shared__ float sh[256];
    int tid = threadIdx.x;
    float s = 0.f;
    for (int i = tid; i < NQ; i += 256) s += g_partial[i];
    sh[tid] = s;
    __syncthreads();
    for (int off = 128; off; off >>= 1) {
        if (tid < off) sh[tid] += sh[tid + off];
        __syncthreads();
    }
    if (tid == 0 && loss_out) loss_out[0] = 1.25f * sh[0] / (float)ZQ_ELEMS;
}

// ---------------- launch (no __device__ symbols below!) ----------------
extern "C" void kernel_launch(void* const* d_in, const int* in_sizes, int n_in,
                              void* d_out, int out_size) {
    const float* z  = (const float*)d_in[0];
    const float* ew = (const float*)d_in[1];
    float* out = (float*)d_out;

    int   write_zq = 0;
    float* lossp = nullptr;
    float* idxf  = nullptr;
    if (out_size >= ZQ_ELEMS) {
        write_zq = 1;
        long R = (long)out_size - (long)ZQ_ELEMS;
        if (R >= (long)NQ + 1)      { lossp = out + ZQ_ELEMS; idxf = out + ZQ_ELEMS + 1; }
        else if (R == (long)NQ)     { idxf = out + ZQ_ELEMS; }
        else if (R >= 1)            { lossp = out + ZQ_ELEMS; }
    } else if (out_size == NQ) {
        idxf = out;
    } else if (out_size == 1) {
        lossp = out;
    }

    static int smem_set = 0;
    if (!smem_set) {
        cudaFuncSetAttribute(screen, cudaFuncAttributeMaxDynamicSharedMemorySize, SMEM_SC);
        smem_set = 1;
    }

    norm_quant<<<NE / 8, 256>>>(ew, NE, 1);
    norm_quant<<<NQ / 8, 256>>>(z, NQ, 0);
    demax_reduce<<<1, 256>>>();
    screen<<<128, 256, SMEM_SC>>>();
    rescore_gather<<<NQ, 256>>>(out, idxf, write_zq);
    finalize_loss<<<1, 256>>>(lossp);
}

// round 10
// speedup vs baseline: 4.4720x; 4.4720x over previous
#include <cuda_runtime.h>
#include <cuda_fp16.h>
#include <cstdint>

#define DIM 256
#define NQ  8192
#define NE  8192
#define NW  64               // 64 int32 words per row (256 int8)
#define ZQ_ELEMS (NQ * DIM)
#define NTILE 32             // code tiles of 256

// smem: As 16K | Bs 2x64K | gmin 32K  = 180224 B
#define AS_OFF   0
#define BS_OFF   16384
#define GMIN_OFF (16384 + 131072)
#define SMEM_SC  (16384 + 131072 + 32768)

// ---------------- device scratch (device-side references only) ----------------
__device__ float g_znorm[NQ * DIM];
__device__ float g_znorm2[NQ];
__device__ float g_zinv[NQ];
__device__ float g_zdel[NQ];
__device__ int   g_qz[NQ * NW];
__device__ float g_enorm[NE * DIM];
__device__ float g_enorm2[NE];
__device__ float g_einv[NE];
__device__ float g_edel[NE];
__device__ int   g_qe[NE * NW];
__device__ float g_demax[1];
__device__ float g_partial[NQ];

// ---------------- L2 normalize + int8 quantize ----------------
__global__ void norm_quant(const float* __restrict__ in, int rows, int is_code) {
    int row  = (blockIdx.x * blockDim.x + threadIdx.x) >> 5;
    int lane = threadIdx.x & 31;
    if (row >= rows) return;
    float* __restrict__ outv = is_code ? g_enorm : g_znorm;
    const float4* src = (const float4*)(in + (size_t)row * DIM);
    float4 v0 = src[lane];
    float4 v1 = src[lane + 32];
    float s = v0.x*v0.x + v0.y*v0.y + v0.z*v0.z + v0.w*v0.w
            + v1.x*v1.x + v1.y*v1.y + v1.z*v1.z + v1.w*v1.w;
    #pragma unroll
    for (int off = 16; off; off >>= 1) s += __shfl_xor_sync(0xffffffffu, s, off);
    float inv = 1.0f / fmaxf(sqrtf(s), 1e-12f);
    v0.x *= inv; v0.y *= inv; v0.z *= inv; v0.w *= inv;
    v1.x *= inv; v1.y *= inv; v1.z *= inv; v1.w *= inv;
    float4* dst = (float4*)(outv + (size_t)row * DIM);
    dst[lane]      = v0;
    dst[lane + 32] = v1;

    float vals[8] = {v0.x, v0.y, v0.z, v0.w, v1.x, v1.y, v1.z, v1.w};
    float s2 = 0.f;
    #pragma unroll
    for (int j = 0; j < 8; j++) s2 += vals[j] * vals[j];
    #pragma unroll
    for (int off = 16; off; off >>= 1) s2 += __shfl_xor_sync(0xffffffffu, s2, off);

    float mx = 0.f;
    #pragma unroll
    for (int j = 0; j < 8; j++) mx = fmaxf(mx, fabsf(vals[j]));
    #pragma unroll
    for (int off = 16; off; off >>= 1) mx = fmaxf(mx, __shfl_xor_sync(0xffffffffu, mx, off));
    float sc    = 127.0f / mx;
    float scinv = mx / 127.0f;

    int h[8];
    float dsum = 0.f;
    #pragma unroll
    for (int j = 0; j < 8; j++) {
        h[j] = (int)rintf(vals[j] * sc);
        float e = vals[j] - (float)h[j] * scinv;
        dsum += e * e;
    }
    #pragma unroll
    for (int off = 16; off; off >>= 1) dsum += __shfl_xor_sync(0xffffffffu, dsum, off);

    int w0 = (h[0] & 0xFF) | ((h[1] & 0xFF) << 8) | ((h[2] & 0xFF) << 16) | (h[3] << 24);
    int w1 = (h[4] & 0xFF) | ((h[5] & 0xFF) << 8) | ((h[6] & 0xFF) << 16) | (h[7] << 24);
    int* qp = is_code ? g_qe : g_qz;
    qp[(size_t)row * NW + lane]      = w0;
    qp[(size_t)row * NW + 32 + lane] = w1;
    if (lane == 0) {
        if (is_code) { g_enorm2[row] = s2; g_einv[row] = scinv; g_edel[row] = sqrtf(dsum); }
        else         { g_znorm2[row] = s2; g_zinv[row] = scinv; g_zdel[row] = sqrtf(dsum); }
    }
}

__global__ void demax_reduce() {
    __shared__ float sh[256];
    int tid = threadIdx.x;
    float m = 0.f;
    for (int i = tid; i < NE; i += 256) m = fmaxf(m, g_edel[i]);
    sh[tid] = m;
    __syncthreads();
    for (int off = 128; off; off >>= 1) {
        if (tid < off) sh[tid] = fmaxf(sh[tid], sh[tid + off]);
        __syncthreads();
    }
    if (tid == 0) g_demax[0] = sh[0];
}

// ---------------- fused dp4a screen + exact select + gather + loss ----------------
// grid 128 x 512 thr. Block: 64 rows x all 8192 codes (32 tiles of 256).
// Warp (wm=wid>>1, wn=wid&1): rows wm*8..+7, cols wn*128 + tx*4 (+3).
// Mainloop stores fp16 min per 32-code group; tail rescans candidate groups exactly.
__global__ __launch_bounds__(512, 1)
void screen(float* __restrict__ zq_out, float* __restrict__ idxf_out, int write_zq) {
    extern __shared__ char smem[];
    int*    As   = (int*)(smem + AS_OFF);     // [64 words][64 rows]
    int*    Bs   = (int*)(smem + BS_OFF);     // [2][64 words][256 codes]
    __half* gmin = (__half*)(smem + GMIN_OFF);// [64 rows][256 groups]

    const int tid = threadIdx.x;
    const int tx  = tid & 31;
    const int wid = tid >> 5;
    const int wm  = wid >> 1;
    const int wn  = wid & 1;
    const int qbase = blockIdx.x * 64;

    // ---- A load, transposed ----
    {
        int row = tid >> 3, p = tid & 7;
        #pragma unroll
        for (int j = 0; j < 2; j++) {
            int w = p * 8 + j * 4;
            int4 v = *(const int4*)&g_qz[(size_t)(qbase + row) * NW + w];
            As[(w + 0) * 64 + row] = v.x;
            As[(w + 1) * 64 + row] = v.y;
            As[(w + 2) * 64 + row] = v.z;
            As[(w + 3) * 64 + row] = v.w;
        }
    }

    // per-row epilogue scalars (rows wm*8 + i)
    float z2s[8], qiv[8];
    #pragma unroll
    for (int i = 0; i < 8; i++) {
        int r = qbase + wm * 8 + i;
        z2s[i] = g_znorm2[r];
        qiv[i] = g_zinv[r];
    }

    // ---- B prologue: tile 0 ----
    const int c  = tid >> 1;      // 0..255
    const int hf = tid & 1;
    {
        #pragma unroll
        for (int j = 0; j < 8; j++) {
            int w = hf * 32 + j * 4;
            int4 v = *(const int4*)&g_qe[(size_t)c * NW + w];
            Bs[(w + 0) * 256 + c] = v.x;
            Bs[(w + 1) * 256 + c] = v.y;
            Bs[(w + 2) * 256 + c] = v.z;
            Bs[(w + 3) * 256 + c] = v.w;
        }
    }
    __syncthreads();

    int acc[8][4];
    int4 br[4];

    #pragma unroll 1
    for (int t = 0; t < NTILE; t++) {
        const int buf = t & 1;
        const int pre = (t + 1 < NTILE);
        #pragma unroll
        for (int i = 0; i < 8; i++) {
            acc[i][0] = 0; acc[i][1] = 0; acc[i][2] = 0; acc[i][3] = 0;
        }
        if (pre) {
            #pragma unroll
            for (int j = 0; j < 4; j++)
                br[j] = *(const int4*)&g_qe[(size_t)((t + 1) * 256 + c) * NW + hf * 32 + j * 4];
        }

        const int* B = Bs + buf * (NW * 256) + wn * 128;
        #pragma unroll 8
        for (int kw = 0; kw < 32; kw++) {
            int4 a0 = *(const int4*)&As[kw * 64 + wm * 8];
            int4 a1 = *(const int4*)&As[kw * 64 + wm * 8 + 4];
            int4 b  = *(const int4*)&B[kw * 256 + tx * 4];
            acc[0][0] = __dp4a(a0.x, b.x, acc[0][0]); acc[0][1] = __dp4a(a0.x, b.y, acc[0][1]);
            acc[0][2] = __dp4a(a0.x, b.z, acc[0][2]); acc[0][3] = __dp4a(a0.x, b.w, acc[0][3]);
            acc[1][0] = __dp4a(a0.y, b.x, acc[1][0]); acc[1][1] = __dp4a(a0.y, b.y, acc[1][1]);
            acc[1][2] = __dp4a(a0.y, b.z, acc[1][2]); acc[1][3] = __dp4a(a0.y, b.w, acc[1][3]);
            acc[2][0] = __dp4a(a0.z, b.x, acc[2][0]); acc[2][1] = __dp4a(a0.z, b.y, acc[2][1]);
            acc[2][2] = __dp4a(a0.z, b.z, acc[2][2]); acc[2][3] = __dp4a(a0.z, b.w, acc[2][3]);
            acc[3][0] = __dp4a(a0.w, b.x, acc[3][0]); acc[3][1] = __dp4a(a0.w, b.y, acc[3][1]);
            acc[3][2] = __dp4a(a0.w, b.z, acc[3][2]); acc[3][3] = __dp4a(a0.w, b.w, acc[3][3]);
            acc[4][0] = __dp4a(a1.x, b.x, acc[4][0]); acc[4][1] = __dp4a(a1.x, b.y, acc[4][1]);
            acc[4][2] = __dp4a(a1.x, b.z, acc[4][2]); acc[4][3] = __dp4a(a1.x, b.w, acc[4][3]);
            acc[5][0] = __dp4a(a1.y, b.x, acc[5][0]); acc[5][1] = __dp4a(a1.y, b.y, acc[5][1]);
            acc[5][2] = __dp4a(a1.y, b.z, acc[5][2]); acc[5][3] = __dp4a(a1.y, b.w, acc[5][3]);
            acc[6][0] = __dp4a(a1.z, b.x, acc[6][0]); acc[6][1] = __dp4a(a1.z, b.y, acc[6][1]);
            acc[6][2] = __dp4a(a1.z, b.z, acc[6][2]); acc[6][3] = __dp4a(a1.z, b.w, acc[6][3]);
            acc[7][0] = __dp4a(a1.w, b.x, acc[7][0]); acc[7][1] = __dp4a(a1.w, b.y, acc[7][1]);
            acc[7][2] = __dp4a(a1.w, b.z, acc[7][2]); acc[7][3] = __dp4a(a1.w, b.w, acc[7][3]);
        }
        if (pre) {
            int* Bn = Bs + ((t + 1) & 1) * (NW * 256);
            #pragma unroll
            for (int j = 0; j < 4; j++) {
                int w = hf * 32 + j * 4;
                Bn[(w + 0) * 256 + c] = br[j].x;
                Bn[(w + 1) * 256 + c] = br[j].y;
                Bn[(w + 2) * 256 + c] = br[j].z;
                Bn[(w + 3) * 256 + c] = br[j].w;
            }
            #pragma unroll
            for (int j = 0; j < 4; j++)
                br[j] = *(const int4*)&g_qe[(size_t)((t + 1) * 256 + c) * NW + hf * 32 + 16 + j * 4];
        }
        #pragma unroll 8
        for (int kw = 32; kw < 64; kw++) {
            int4 a0 = *(const int4*)&As[kw * 64 + wm * 8];
            int4 a1 = *(const int4*)&As[kw * 64 + wm * 8 + 4];
            int4 b  = *(const int4*)&B[kw * 256 + tx * 4];
            acc[0][0] = __dp4a(a0.x, b.x, acc[0][0]); acc[0][1] = __dp4a(a0.x, b.y, acc[0][1]);
            acc[0][2] = __dp4a(a0.x, b.z, acc[0][2]); acc[0][3] = __dp4a(a0.x, b.w, acc[0][3]);
            acc[1][0] = __dp4a(a0.y, b.x, acc[1][0]); acc[1][1] = __dp4a(a0.y, b.y, acc[1][1]);
            acc[1][2] = __dp4a(a0.y, b.z, acc[1][2]); acc[1][3] = __dp4a(a0.y, b.w, acc[1][3]);
            acc[2][0] = __dp4a(a0.z, b.x, acc[2][0]); acc[2][1] = __dp4a(a0.z, b.y, acc[2][1]);
            acc[2][2] = __dp4a(a0.z, b.z, acc[2][2]); acc[2][3] = __dp4a(a0.z, b.w, acc[2][3]);
            acc[3][0] = __dp4a(a0.w, b.x, acc[3][0]); acc[3][1] = __dp4a(a0.w, b.y, acc[3][1]);
            acc[3][2] = __dp4a(a0.w, b.z, acc[3][2]); acc[3][3] = __dp4a(a0.w, b.w, acc[3][3]);
            acc[4][0] = __dp4a(a1.x, b.x, acc[4][0]); acc[4][1] = __dp4a(a1.x, b.y, acc[4][1]);
            acc[4][2] = __dp4a(a1.x, b.z, acc[4][2]); acc[4][3] = __dp4a(a1.x, b.w, acc[4][3]);
            acc[5][0] = __dp4a(a1.y, b.x, acc[5][0]); acc[5][1] = __dp4a(a1.y, b.y, acc[5][1]);
            acc[5][2] = __dp4a(a1.y, b.z, acc[5][2]); acc[5][3] = __dp4a(a1.y, b.w, acc[5][3]);
            acc[6][0] = __dp4a(a1.z, b.x, acc[6][0]); acc[6][1] = __dp4a(a1.z, b.y, acc[6][1]);
            acc[6][2] = __dp4a(a1.z, b.z, acc[6][2]); acc[6][3] = __dp4a(a1.z, b.w, acc[6][3]);
            acc[7][0] = __dp4a(a1.w, b.x, acc[7][0]); acc[7][1] = __dp4a(a1.w, b.y, acc[7][1]);
            acc[7][2] = __dp4a(a1.w, b.z, acc[7][2]); acc[7][3] = __dp4a(a1.w, b.w, acc[7][3]);
        }
        if (pre) {
            int* Bn = Bs + ((t + 1) & 1) * (NW * 256);
            #pragma unroll
            for (int j = 0; j < 4; j++) {
                int w = hf * 32 + 16 + j * 4;
                Bn[(w + 0) * 256 + c] = br[j].x;
                Bn[(w + 1) * 256 + c] = br[j].y;
                Bn[(w + 2) * 256 + c] = br[j].z;
                Bn[(w + 3) * 256 + c] = br[j].w;
            }
        }
        __syncthreads();

        // ---- epilogue: per-row per-32-code-group fp16 min ----
        int colb = t * 256 + wn * 128 + tx * 4;
        float4 e2  = *(const float4*)&g_enorm2[colb];
        float4 civ = *(const float4*)&g_einv[colb];
        int ggroup = t * 8 + wn * 4 + (tx >> 3);
        #pragma unroll
        for (int i = 0; i < 8; i++) {
            float sc = qiv[i];
            float k0 = z2s[i] + e2.x - 2.0f * ((float)acc[i][0] * (sc * civ.x));
            float k1 = z2s[i] + e2.y - 2.0f * ((float)acc[i][1] * (sc * civ.y));
            float k2 = z2s[i] + e2.z - 2.0f * ((float)acc[i][2] * (sc * civ.z));
            float k3 = z2s[i] + e2.w - 2.0f * ((float)acc[i][3] * (sc * civ.w));
            float m = fminf(fminf(k0, k1), fminf(k2, k3));
            m = fminf(m, __shfl_xor_sync(0xffffffffu, m, 1));
            m = fminf(m, __shfl_xor_sync(0xffffffffu, m, 2));
            m = fminf(m, __shfl_xor_sync(0xffffffffu, m, 4));
            if ((tx & 7) == 0)
                gmin[(wm * 8 + i) * 256 + ggroup] = __float2half(m);
        }
    }
    __syncthreads();

    // ---- tail: per-warp 4 rows — exact select + gather + loss ----
    float D = g_demax[0];
    #pragma unroll 1
    for (int k = 0; k < 4; k++) {
        int r    = wid * 4 + k;
        int rowg = qbase + r;

        // best approx key over groups
        const __half* gr = &gmin[r * 256];
        float mf[8];
        {
            uint4 v = *(const uint4*)&gr[tx * 8];
            __half2 h0 = *(__half2*)&v.x, h1 = *(__half2*)&v.y;
            __half2 h2 = *(__half2*)&v.z, h3 = *(__half2*)&v.w;
            float2 f0 = __half22float2(h0), f1 = __half22float2(h1);
            float2 f2 = __half22float2(h2), f3 = __half22float2(h3);
            mf[0] = f0.x; mf[1] = f0.y; mf[2] = f1.x; mf[3] = f1.y;
            mf[4] = f2.x; mf[5] = f2.y; mf[6] = f3.x; mf[7] = f3.y;
        }
        float lm = mf[0];
        #pragma unroll
        for (int j = 1; j < 8; j++) lm = fminf(lm, mf[j]);
        #pragma unroll
        for (int off = 16; off; off >>= 1) lm = fminf(lm, __shfl_xor_sync(0xffffffffu, lm, off));

        float dq  = g_zdel[rowg];
        float thr = lm + 4.0f * (dq + D + 3.0f * dq * D) + 0.012f;   // margin + fp16 slack

        float z2r = g_znorm2[rowg];
        const float4* zv = (const float4*)&g_znorm[(size_t)rowg * DIM];
        unsigned long long lbest = 0xFFFFFFFFFFFFFFFFull;

        #pragma unroll 1
        for (int g = 0; g < 256; g++) {
            float gm = __half2float(gr[g]);
            if (gm <= thr) {
                int code = g * 32 + tx;
                const float4* ev = (const float4*)&g_enorm[(size_t)code * DIM];
                float d0 = 0.f, d1 = 0.f, d2 = 0.f, d3 = 0.f;
                #pragma unroll 8
                for (int d = 0; d < 64; d += 4) {
                    float4 z0 = zv[d],     e0 = ev[d];
                    float4 z1 = zv[d + 1], e1 = ev[d + 1];
                    float4 z2 = zv[d + 2], e2v = ev[d + 2];
                    float4 z3 = zv[d + 3], e3 = ev[d + 3];
                    d0 += z0.x*e0.x + z0.y*e0.y + z0.z*e0.z + z0.w*e0.w;
                    d1 += z1.x*e1.x + z1.y*e1.y + z1.z*e1.z + z1.w*e1.w;
                    d2 += z2.x*e2v.x + z2.y*e2v.y + z2.z*e2v.z + z2.w*e2v.w;
                    d3 += z3.x*e3.x + z3.y*e3.y + z3.z*e3.z + z3.w*e3.w;
                }
                float key = z2r + g_enorm2[code] - 2.0f * (d0 + d1 + d2 + d3);
                unsigned long long p =
                    ((unsigned long long)__float_as_uint(key + 1.0f) << 32) | (unsigned)code;
                lbest = min(lbest, p);
            }
        }
        #pragma unroll
        for (int off = 16; off; off >>= 1) {
            unsigned long long o = __shfl_xor_sync(0xffffffffu, lbest, off);
            lbest = min(lbest, o);
        }
        int e = (int)(lbest & 0xFFFFFFFFull) & (NE - 1);

        // gather + loss partial
        const float4* evw = (const float4*)&g_enorm[(size_t)e * DIM];
        float4 a0 = evw[tx], a1 = evw[tx + 32];
        float4 b0 = zv[tx],  b1 = zv[tx + 32];
        if (write_zq) {
            float4* o = (float4*)&zq_out[(size_t)rowg * DIM];
            o[tx]      = a0;
            o[tx + 32] = a1;
        }
        float dx, s = 0.f;
        dx = a0.x - b0.x; s += dx * dx;  dx = a0.y - b0.y; s += dx * dx;
        dx = a0.z - b0.z; s += dx * dx;  dx = a0.w - b0.w; s += dx * dx;
        dx = a1.x - b1.x; s += dx * dx;  dx = a1.y - b1.y; s += dx * dx;
        dx = a1.z - b1.z; s += dx * dx;  dx = a1.w - b1.w; s += dx * dx;
        #pragma unroll
        for (int off = 16; off; off >>= 1) s += __shfl_xor_sync(0xffffffffu, s, off);
        if (tx == 0) {
            g_partial[rowg] = s;
            if (idxf_out) idxf_out[rowg] = (float)e;
        }
    }
}

__global__ void finalize_loss(float* __restrict__ loss_out) {
    __shared__ float sh[256];
    int tid = threadIdx.x;
    float s = 0.f;
    for (int i = tid; i < NQ; i += 256) s += g_partial[i];
    sh[tid] = s;
    __syncthreads();
    for (int off = 128; off; off >>= 1) {
        if (tid < off) sh[tid] += sh[tid + off];
        __syncthreads();
    }
    if (tid == 0 && loss_out) loss_out[0] = 1.25f * sh[0] / (float)ZQ_ELEMS;
}

// ---------------- launch (no __device__ symbols below!) ----------------
extern "C" void kernel_launch(void* const* d_in, const int* in_sizes, int n_in,
                              void* d_out, int out_size) {
    const float* z  = (const float*)d_in[0];
    const float* ew = (const float*)d_in[1];
    float* out = (float*)d_out;

    int   write_zq = 0;
    float* lossp = nullptr;
    float* idxf  = nullptr;
    if (out_size >= ZQ_ELEMS) {
        write_zq = 1;
        long R = (long)out_size - (long)ZQ_ELEMS;
        if (R >= (long)NQ + 1)      { lossp = out + ZQ_ELEMS; idxf = out + ZQ_ELEMS + 1; }
        else if (R == (long)NQ)     { idxf = out + ZQ_ELEMS; }
        else if (R >= 1)            { lossp = out + ZQ_ELEMS; }
    } else if (out_size == NQ) {
        idxf = out;
    } else if (out_size == 1) {
        lossp = out;
    }

    static int smem_set = 0;
    if (!smem_set) {
        cudaFuncSetAttribute(screen, cudaFuncAttributeMaxDynamicSharedMemorySize, SMEM_SC);
        smem_set = 1;
    }

    norm_quant<<<NE / 8, 256>>>(ew, NE, 1);
    norm_quant<<<NQ / 8, 256>>>(z, NQ, 0);
    demax_reduce<<<1, 256>>>();
    screen<<<128, 512, SMEM_SC>>>(out, idxf, write_zq);
    finalize_loss<<<1, 256>>>(lossp);
}

// round 11
// speedup vs baseline: 5.2290x; 1.1693x over previous
#include <cuda_runtime.h>
#include <cstdint>

#define DIM 256
#define NQ  8192
#define NE  8192
#define NW  64               // 64 int32 words per row (256 int8)
#define ZQ_ELEMS (NQ * DIM)
#define NTILE 32             // code tiles of 256
#define NBLK  128
#define NTHR  512

// smem: As 16K | Bs 2x64K | gmin(fp32) 64K = 212992 B
#define AS_OFF   0
#define BS_OFF   16384
#define GM_OFF   (16384 + 131072)
#define SMEM_SC  (16384 + 131072 + 65536)

// ---------------- device scratch (device-side references only) ----------------
__device__ float g_znorm[NQ * DIM];
__device__ float g_znorm2[NQ];
__device__ float g_zinv[NQ];
__device__ float g_zdel[NQ];
__device__ int   g_qz[NQ * NW];
__device__ float g_enorm[NE * DIM];
__device__ float g_enorm2[NE];
__device__ float g_einv[NE];
__device__ int   g_qe[NE * NW];
__device__ unsigned g_demaxU;        // atomicMax of float bits (idempotent across replays)
__device__ float g_partial[NQ];
__device__ unsigned g_count;         // barrier arrive counter (returns to 0 each use)
__device__ unsigned g_gen;           // barrier generation (monotonic; gen0-relative waits)

// ---------------- grid barrier (all NBLK blocks co-resident: 1 block/SM) ----------
__device__ __forceinline__ void gridbar(unsigned expect) {
    __threadfence();
    __syncthreads();
    if (threadIdx.x == 0) {
        unsigned t = atomicAdd(&g_count, 1);
        if (t == NBLK - 1) {
            g_count = 0;
            __threadfence();
            atomicAdd(&g_gen, 1);
        } else {
            while (atomicAdd(&g_gen, 0) < expect) { }
            __threadfence();
        }
    }
    __syncthreads();
}

// ---------------- the whole pipeline in ONE kernel ----------------
__global__ __launch_bounds__(NTHR, 1)
void vq_fused(const float* __restrict__ z_in, const float* __restrict__ e_in,
              float* __restrict__ zq_out, float* __restrict__ idxf_out,
              float* __restrict__ loss_out, int write_zq) {
    extern __shared__ char smem[];
    int*   As     = (int*)(smem + AS_OFF);     // [64 words][64 rows]
    int*   Bs     = (int*)(smem + BS_OFF);     // [2][64 words][256 codes]
    float* gmin32 = (float*)(smem + GM_OFF);   // [64 rows][256 groups]
    __shared__ unsigned s_gen0;

    const int tid = threadIdx.x;
    const int tx  = tid & 31;
    const int wid = tid >> 5;

    if (tid == 0) s_gen0 = g_gen;    // stable: no block can bump gen before all start
    __syncthreads();
    const unsigned gen0 = s_gen0;

    // ================= Phase 1: L2-normalize + int8 quantize (16384 rows) ======
    {
        int warpG = blockIdx.x * 16 + wid;           // 0..2047
        #pragma unroll 1
        for (int it = 0; it < 8; it++) {
            int r16 = warpG + it * 2048;             // 0..16383
            int is_code = (r16 < NE);
            int row = is_code ? r16 : (r16 - NE);
            const float* in = is_code ? e_in : z_in;
            float* outv = is_code ? g_enorm : g_znorm;

            const float4* src = (const float4*)(in + (size_t)row * DIM);
            float4 v0 = src[tx];
            float4 v1 = src[tx + 32];
            float s = v0.x*v0.x + v0.y*v0.y + v0.z*v0.z + v0.w*v0.w
                    + v1.x*v1.x + v1.y*v1.y + v1.z*v1.z + v1.w*v1.w;
            #pragma unroll
            for (int off = 16; off; off >>= 1) s += __shfl_xor_sync(0xffffffffu, s, off);
            float inv = 1.0f / fmaxf(sqrtf(s), 1e-12f);
            v0.x *= inv; v0.y *= inv; v0.z *= inv; v0.w *= inv;
            v1.x *= inv; v1.y *= inv; v1.z *= inv; v1.w *= inv;
            float4* dst = (float4*)(outv + (size_t)row * DIM);
            dst[tx]      = v0;
            dst[tx + 32] = v1;

            float vals[8] = {v0.x, v0.y, v0.z, v0.w, v1.x, v1.y, v1.z, v1.w};
            float s2 = 0.f;
            #pragma unroll
            for (int j = 0; j < 8; j++) s2 += vals[j] * vals[j];
            #pragma unroll
            for (int off = 16; off; off >>= 1) s2 += __shfl_xor_sync(0xffffffffu, s2, off);

            float mx = 0.f;
            #pragma unroll
            for (int j = 0; j < 8; j++) mx = fmaxf(mx, fabsf(vals[j]));
            #pragma unroll
            for (int off = 16; off; off >>= 1) mx = fmaxf(mx, __shfl_xor_sync(0xffffffffu, mx, off));
            float sc    = 127.0f / mx;
            float scinv = mx / 127.0f;

            int h[8];
            float dsum = 0.f;
            #pragma unroll
            for (int j = 0; j < 8; j++) {
                h[j] = (int)rintf(vals[j] * sc);
                float e = vals[j] - (float)h[j] * scinv;
                dsum += e * e;
            }
            #pragma unroll
            for (int off = 16; off; off >>= 1) dsum += __shfl_xor_sync(0xffffffffu, dsum, off);

            int w0 = (h[0] & 0xFF) | ((h[1] & 0xFF) << 8) | ((h[2] & 0xFF) << 16) | (h[3] << 24);
            int w1 = (h[4] & 0xFF) | ((h[5] & 0xFF) << 8) | ((h[6] & 0xFF) << 16) | (h[7] << 24);
            int* qp = is_code ? g_qe : g_qz;
            qp[(size_t)row * NW + tx]      = w0;
            qp[(size_t)row * NW + 32 + tx] = w1;
            if (tx == 0) {
                float del = sqrtf(dsum);
                if (is_code) {
                    g_enorm2[row] = s2; g_einv[row] = scinv;
                    atomicMax(&g_demaxU, __float_as_uint(del));
                } else {
                    g_znorm2[row] = s2; g_zinv[row] = scinv; g_zdel[row] = del;
                }
            }
        }
    }
    gridbar(gen0 + 1);

    // ================= Phase 2: dp4a screen + exact select + gather + loss =====
    const int wm = wid >> 1;
    const int wn = wid & 1;
    const int qbase = blockIdx.x * 64;

    // A load, transposed
    {
        int row = tid >> 3, p = tid & 7;
        #pragma unroll
        for (int j = 0; j < 2; j++) {
            int w = p * 8 + j * 4;
            int4 v = *(const int4*)&g_qz[(size_t)(qbase + row) * NW + w];
            As[(w + 0) * 64 + row] = v.x;
            As[(w + 1) * 64 + row] = v.y;
            As[(w + 2) * 64 + row] = v.z;
            As[(w + 3) * 64 + row] = v.w;
        }
    }

    float z2s[8], qiv[8];
    #pragma unroll
    for (int i = 0; i < 8; i++) {
        int r = qbase + wm * 8 + i;
        z2s[i] = g_znorm2[r];
        qiv[i] = g_zinv[r];
    }

    // B prologue: tile 0
    const int c  = tid >> 1;      // 0..255
    const int hf = tid & 1;
    {
        #pragma unroll
        for (int j = 0; j < 8; j++) {
            int w = hf * 32 + j * 4;
            int4 v = *(const int4*)&g_qe[(size_t)c * NW + w];
            Bs[(w + 0) * 256 + c] = v.x;
            Bs[(w + 1) * 256 + c] = v.y;
            Bs[(w + 2) * 256 + c] = v.z;
            Bs[(w + 3) * 256 + c] = v.w;
        }
    }
    __syncthreads();

    int acc[8][4];
    int4 br[4];

    #pragma unroll 1
    for (int t = 0; t < NTILE; t++) {
        const int buf = t & 1;
        const int pre = (t + 1 < NTILE);
        #pragma unroll
        for (int i = 0; i < 8; i++) {
            acc[i][0] = 0; acc[i][1] = 0; acc[i][2] = 0; acc[i][3] = 0;
        }
        if (pre) {
            #pragma unroll
            for (int j = 0; j < 4; j++)
                br[j] = *(const int4*)&g_qe[(size_t)((t + 1) * 256 + c) * NW + hf * 32 + j * 4];
        }

        const int* B = Bs + buf * (NW * 256) + wn * 128;
        #pragma unroll 8
        for (int kw = 0; kw < 32; kw++) {
            int4 a0 = *(const int4*)&As[kw * 64 + wm * 8];
            int4 a1 = *(const int4*)&As[kw * 64 + wm * 8 + 4];
            int4 b  = *(const int4*)&B[kw * 256 + tx * 4];
            acc[0][0] = __dp4a(a0.x, b.x, acc[0][0]); acc[0][1] = __dp4a(a0.x, b.y, acc[0][1]);
            acc[0][2] = __dp4a(a0.x, b.z, acc[0][2]); acc[0][3] = __dp4a(a0.x, b.w, acc[0][3]);
            acc[1][0] = __dp4a(a0.y, b.x, acc[1][0]); acc[1][1] = __dp4a(a0.y, b.y, acc[1][1]);
            acc[1][2] = __dp4a(a0.y, b.z, acc[1][2]); acc[1][3] = __dp4a(a0.y, b.w, acc[1][3]);
            acc[2][0] = __dp4a(a0.z, b.x, acc[2][0]); acc[2][1] = __dp4a(a0.z, b.y, acc[2][1]);
            acc[2][2] = __dp4a(a0.z, b.z, acc[2][2]); acc[2][3] = __dp4a(a0.z, b.w, acc[2][3]);
            acc[3][0] = __dp4a(a0.w, b.x, acc[3][0]); acc[3][1] = __dp4a(a0.w, b.y, acc[3][1]);
            acc[3][2] = __dp4a(a0.w, b.z, acc[3][2]); acc[3][3] = __dp4a(a0.w, b.w, acc[3][3]);
            acc[4][0] = __dp4a(a1.x, b.x, acc[4][0]); acc[4][1] = __dp4a(a1.x, b.y, acc[4][1]);
            acc[4][2] = __dp4a(a1.x, b.z, acc[4][2]); acc[4][3] = __dp4a(a1.x, b.w, acc[4][3]);
            acc[5][0] = __dp4a(a1.y, b.x, acc[5][0]); acc[5][1] = __dp4a(a1.y, b.y, acc[5][1]);
            acc[5][2] = __dp4a(a1.y, b.z, acc[5][2]); acc[5][3] = __dp4a(a1.y, b.w, acc[5][3]);
            acc[6][0] = __dp4a(a1.z, b.x, acc[6][0]); acc[6][1] = __dp4a(a1.z, b.y, acc[6][1]);
            acc[6][2] = __dp4a(a1.z, b.z, acc[6][2]); acc[6][3] = __dp4a(a1.z, b.w, acc[6][3]);
            acc[7][0] = __dp4a(a1.w, b.x, acc[7][0]); acc[7][1] = __dp4a(a1.w, b.y, acc[7][1]);
            acc[7][2] = __dp4a(a1.w, b.z, acc[7][2]); acc[7][3] = __dp4a(a1.w, b.w, acc[7][3]);
        }
        if (pre) {
            int* Bn = Bs + ((t + 1) & 1) * (NW * 256);
            #pragma unroll
            for (int j = 0; j < 4; j++) {
                int w = hf * 32 + j * 4;
                Bn[(w + 0) * 256 + c] = br[j].x;
                Bn[(w + 1) * 256 + c] = br[j].y;
                Bn[(w + 2) * 256 + c] = br[j].z;
                Bn[(w + 3) * 256 + c] = br[j].w;
            }
            #pragma unroll
            for (int j = 0; j < 4; j++)
                br[j] = *(const int4*)&g_qe[(size_t)((t + 1) * 256 + c) * NW + hf * 32 + 16 + j * 4];
        }
        #pragma unroll 8
        for (int kw = 32; kw < 64; kw++) {
            int4 a0 = *(const int4*)&As[kw * 64 + wm * 8];
            int4 a1 = *(const int4*)&As[kw * 64 + wm * 8 + 4];
            int4 b  = *(const int4*)&B[kw * 256 + tx * 4];
            acc[0][0] = __dp4a(a0.x, b.x, acc[0][0]); acc[0][1] = __dp4a(a0.x, b.y, acc[0][1]);
            acc[0][2] = __dp4a(a0.x, b.z, acc[0][2]); acc[0][3] = __dp4a(a0.x, b.w, acc[0][3]);
            acc[1][0] = __dp4a(a0.y, b.x, acc[1][0]); acc[1][1] = __dp4a(a0.y, b.y, acc[1][1]);
            acc[1][2] = __dp4a(a0.y, b.z, acc[1][2]); acc[1][3] = __dp4a(a0.y, b.w, acc[1][3]);
            acc[2][0] = __dp4a(a0.z, b.x, acc[2][0]); acc[2][1] = __dp4a(a0.z, b.y, acc[2][1]);
            acc[2][2] = __dp4a(a0.z, b.z, acc[2][2]); acc[2][3] = __dp4a(a0.z, b.w, acc[2][3]);
            acc[3][0] = __dp4a(a0.w, b.x, acc[3][0]); acc[3][1] = __dp4a(a0.w, b.y, acc[3][1]);
            acc[3][2] = __dp4a(a0.w, b.z, acc[3][2]); acc[3][3] = __dp4a(a0.w, b.w, acc[3][3]);
            acc[4][0] = __dp4a(a1.x, b.x, acc[4][0]); acc[4][1] = __dp4a(a1.x, b.y, acc[4][1]);
            acc[4][2] = __dp4a(a1.x, b.z, acc[4][2]); acc[4][3] = __dp4a(a1.x, b.w, acc[4][3]);
            acc[5][0] = __dp4a(a1.y, b.x, acc[5][0]); acc[5][1] = __dp4a(a1.y, b.y, acc[5][1]);
            acc[5][2] = __dp4a(a1.y, b.z, acc[5][2]); acc[5][3] = __dp4a(a1.y, b.w, acc[5][3]);
            acc[6][0] = __dp4a(a1.z, b.x, acc[6][0]); acc[6][1] = __dp4a(a1.z, b.y, acc[6][1]);
            acc[6][2] = __dp4a(a1.z, b.z, acc[6][2]); acc[6][3] = __dp4a(a1.z, b.w, acc[6][3]);
            acc[7][0] = __dp4a(a1.w, b.x, acc[7][0]); acc[7][1] = __dp4a(a1.w, b.y, acc[7][1]);
            acc[7][2] = __dp4a(a1.w, b.z, acc[7][2]); acc[7][3] = __dp4a(a1.w, b.w, acc[7][3]);
        }
        if (pre) {
            int* Bn = Bs + ((t + 1) & 1) * (NW * 256);
            #pragma unroll
            for (int j = 0; j < 4; j++) {
                int w = hf * 32 + 16 + j * 4;
                Bn[(w + 0) * 256 + c] = br[j].x;
                Bn[(w + 1) * 256 + c] = br[j].y;
                Bn[(w + 2) * 256 + c] = br[j].z;
                Bn[(w + 3) * 256 + c] = br[j].w;
            }
        }
        __syncthreads();

        // per-row per-32-code-group fp32 min
        int colb = t * 256 + wn * 128 + tx * 4;
        float4 e2  = *(const float4*)&g_enorm2[colb];
        float4 civ = *(const float4*)&g_einv[colb];
        int ggroup = t * 8 + wn * 4 + (tx >> 3);
        #pragma unroll
        for (int i = 0; i < 8; i++) {
            float sc = qiv[i];
            float k0 = z2s[i] + e2.x - 2.0f * ((float)acc[i][0] * (sc * civ.x));
            float k1 = z2s[i] + e2.y - 2.0f * ((float)acc[i][1] * (sc * civ.y));
            float k2 = z2s[i] + e2.z - 2.0f * ((float)acc[i][2] * (sc * civ.z));
            float k3 = z2s[i] + e2.w - 2.0f * ((float)acc[i][3] * (sc * civ.w));
            float m = fminf(fminf(k0, k1), fminf(k2, k3));
            m = fminf(m, __shfl_xor_sync(0xffffffffu, m, 1));
            m = fminf(m, __shfl_xor_sync(0xffffffffu, m, 2));
            m = fminf(m, __shfl_xor_sync(0xffffffffu, m, 4));
            if ((tx & 7) == 0)
                gmin32[(wm * 8 + i) * 256 + ggroup] = m;
        }
    }
    __syncthreads();

    // ---- tail: per-warp 4 rows, exact select (warp-per-code, coalesced) ----
    {
        float D = __uint_as_float(g_demaxU);
        #pragma unroll 1
        for (int k = 0; k < 4; k++) {
            int r    = wid * 4 + k;
            int rowg = qbase + r;
            const float* gr = &gmin32[r * 256];

            float4 ga = *(const float4*)&gr[tx * 8];
            float4 gb = *(const float4*)&gr[tx * 8 + 4];
            float lm = fminf(fminf(fminf(ga.x, ga.y), fminf(ga.z, ga.w)),
                             fminf(fminf(gb.x, gb.y), fminf(gb.z, gb.w)));
            #pragma unroll
            for (int off = 16; off; off >>= 1) lm = fminf(lm, __shfl_xor_sync(0xffffffffu, lm, off));

            float dq = g_zdel[rowg];
            float M  = 2.0f * (dq + D + dq * D);       // sound per-key error bound
            float thr = lm + 2.0f * M + 2e-5f;         // sound capture window + fp slack

            float z2r = g_znorm2[rowg];
            const float4* zvw = (const float4*)&g_znorm[(size_t)rowg * DIM];
            float4 za = zvw[tx], zb = zvw[tx + 32];
            unsigned long long lbest = 0xFFFFFFFFFFFFFFFFull;

            #pragma unroll 1
            for (int g = 0; g < 256; g++) {
                if (gr[g] <= thr) {
                    #pragma unroll 1
                    for (int c8 = 0; c8 < 32; c8++) {
                        int code = g * 32 + c8;
                        const float4* ev = (const float4*)&g_enorm[(size_t)code * DIM];
                        float4 ea = ev[tx], eb = ev[tx + 32];
                        float d = za.x*ea.x + za.y*ea.y + za.z*ea.z + za.w*ea.w
                                + zb.x*eb.x + zb.y*eb.y + zb.z*eb.z + zb.w*eb.w;
                        #pragma unroll
                        for (int off = 16; off; off >>= 1)
                            d += __shfl_xor_sync(0xffffffffu, d, off);
                        float key = z2r + g_enorm2[code] - 2.0f * d;
                        unsigned long long p =
                            ((unsigned long long)__float_as_uint(key) << 32) | (unsigned)code;
                        lbest = min(lbest, p);
                    }
                }
            }
            int e = (int)(lbest & 0xFFFFFFFFull) & (NE - 1);

            // gather + loss partial
            const float4* evw = (const float4*)&g_enorm[(size_t)e * DIM];
            float4 a0 = evw[tx], a1 = evw[tx + 32];
            if (write_zq) {
                float4* o = (float4*)&zq_out[(size_t)rowg * DIM];
                o[tx]      = a0;
                o[tx + 32] = a1;
            }
            float dx, s = 0.f;
            dx = a0.x - za.x; s += dx * dx;  dx = a0.y - za.y; s += dx * dx;
            dx = a0.z - za.z; s += dx * dx;  dx = a0.w - za.w; s += dx * dx;
            dx = a1.x - zb.x; s += dx * dx;  dx = a1.y - zb.y; s += dx * dx;
            dx = a1.z - zb.z; s += dx * dx;  dx = a1.w - zb.w; s += dx * dx;
            #pragma unroll
            for (int off = 16; off; off >>= 1) s += __shfl_xor_sync(0xffffffffu, s, off);
            if (tx == 0) {
                g_partial[rowg] = s;
                if (idxf_out) idxf_out[rowg] = (float)e;
            }
        }
    }
    gridbar(gen0 + 2);

    // ================= Phase 3: loss finalize (block 0) ========================
    if (blockIdx.x == 0) {
        float* red = (float*)smem;
        float s = 0.f;
        for (int i = tid; i < NQ; i += NTHR) s += g_partial[i];
        red[tid] = s;
        __syncthreads();
        for (int off = NTHR / 2; off; off >>= 1) {
            if (tid < off) red[tid] += red[tid + off];
            __syncthreads();
        }
        if (tid == 0 && loss_out) loss_out[0] = 1.25f * red[0] / (float)ZQ_ELEMS;
    }
}

// ---------------- launch (no __device__ symbols below!) ----------------
extern "C" void kernel_launch(void* const* d_in, const int* in_sizes, int n_in,
                              void* d_out, int out_size) {
    const float* z  = (const float*)d_in[0];
    const float* ew = (const float*)d_in[1];
    float* out = (float*)d_out;

    int   write_zq = 0;
    float* lossp = nullptr;
    float* idxf  = nullptr;
    if (out_size >= ZQ_ELEMS) {
        write_zq = 1;
        long R = (long)out_size - (long)ZQ_ELEMS;
        if (R >= (long)NQ + 1)      { lossp = out + ZQ_ELEMS; idxf = out + ZQ_ELEMS + 1; }
        else if (R == (long)NQ)     { idxf = out + ZQ_ELEMS; }
        else if (R >= 1)            { lossp = out + ZQ_ELEMS; }
    } else if (out_size == NQ) {
        idxf = out;
    } else if (out_size == 1) {
        lossp = out;
    }

    static int smem_set = 0;
    if (!smem_set) {
        cudaFuncSetAttribute(vq_fused, cudaFuncAttributeMaxDynamicSharedMemorySize, SMEM_SC);
        smem_set = 1;
    }

    vq_fused<<<NBLK, NTHR, SMEM_SC>>>(z, ew, out, idxf, lossp, write_zq);
}

// round 12
// speedup vs baseline: 14.0328x; 2.6836x over previous
#include <cuda_runtime.h>
#include <cuda_fp16.h>
#include <cstdint>

#define DIM 256
#define NQ  8192
#define NE  8192
#define NW  64               // 64 int32 words per row (256 int8)
#define ZQ_ELEMS (NQ * DIM)
#define NTILE 32             // code tiles of 256
#define NBLK  128
#define NTHR  1024
#define LIST_CAP 4096

// smem: As 16K | Bs 64K (single) | gmin8 fp16 64x1024 = 128K  -> 212992 B
#define AS_OFF   0
#define BS_OFF   16384
#define GM_OFF   (16384 + 65536)
#define SMEM_SC  (16384 + 65536 + 131072)

// ---------------- device scratch (device-side references only) ----------------
__device__ float g_znorm[NQ * DIM];
__device__ float g_znorm2[NQ];
__device__ float g_zinv[NQ];
__device__ float g_zdel[NQ];
__device__ int   g_qz[NQ * NW];
__device__ float g_enorm[NE * DIM];
__device__ float g_enorm2[NE];
__device__ float g_einv[NE];
__device__ int   g_qe[NE * NW];
__device__ unsigned g_demaxU;        // atomicMax of float bits (idempotent across replays)
__device__ float g_partial[NQ];
__device__ unsigned g_count;
__device__ unsigned g_gen;

// ---------------- grid barrier (128 blocks co-resident: 1 block/SM) ----------
__device__ __forceinline__ void gridbar(unsigned expect) {
    __threadfence();
    __syncthreads();
    if (threadIdx.x == 0) {
        unsigned t = atomicAdd(&g_count, 1);
        if (t == NBLK - 1) {
            g_count = 0;
            __threadfence();
            atomicAdd(&g_gen, 1);
        } else {
            while (atomicAdd(&g_gen, 0) < expect) { }
            __threadfence();
        }
    }
    __syncthreads();
}

// ---------------- the whole pipeline in ONE kernel ----------------
__global__ __launch_bounds__(NTHR, 1)
void vq_fused(const float* __restrict__ z_in, const float* __restrict__ e_in,
              float* __restrict__ zq_out, float* __restrict__ idxf_out,
              float* __restrict__ loss_out, int write_zq) {
    extern __shared__ char smem[];
    int*    As     = (int*)(smem + AS_OFF);     // [64 words][64 rows]
    int*    Bs     = (int*)(smem + BS_OFF);     // [64 words][256 codes] single buffer
    __half* gmin8  = (__half*)(smem + GM_OFF);  // [64 rows][1024 groups-of-8]
    __shared__ float s_thr[64];
    __shared__ unsigned long long s_best[64];
    __shared__ int s_cnt;
    __shared__ unsigned s_gen0;

    const int tid = threadIdx.x;
    const int tx  = tid & 31;
    const int wid = tid >> 5;

    if (tid == 0) s_gen0 = g_gen;
    __syncthreads();
    const unsigned gen0 = s_gen0;

    // ================= Phase 1: L2-normalize + int8 quantize (16384 rows) ======
    {
        int warpG = blockIdx.x * 32 + wid;            // 0..4095
        #pragma unroll 1
        for (int it = 0; it < 4; it++) {
            int r16 = warpG + it * 4096;              // 0..16383
            int is_code = (r16 < NE);
            int row = is_code ? r16 : (r16 - NE);
            const float* in = is_code ? e_in : z_in;
            float* outv = is_code ? g_enorm : g_znorm;

            const float4* src = (const float4*)(in + (size_t)row * DIM);
            float4 v0 = src[tx];
            float4 v1 = src[tx + 32];
            float s = v0.x*v0.x + v0.y*v0.y + v0.z*v0.z + v0.w*v0.w
                    + v1.x*v1.x + v1.y*v1.y + v1.z*v1.z + v1.w*v1.w;
            #pragma unroll
            for (int off = 16; off; off >>= 1) s += __shfl_xor_sync(0xffffffffu, s, off);
            float inv = 1.0f / fmaxf(sqrtf(s), 1e-12f);
            v0.x *= inv; v0.y *= inv; v0.z *= inv; v0.w *= inv;
            v1.x *= inv; v1.y *= inv; v1.z *= inv; v1.w *= inv;
            float4* dst = (float4*)(outv + (size_t)row * DIM);
            dst[tx]      = v0;
            dst[tx + 32] = v1;

            float vals[8] = {v0.x, v0.y, v0.z, v0.w, v1.x, v1.y, v1.z, v1.w};
            float s2 = 0.f;
            #pragma unroll
            for (int j = 0; j < 8; j++) s2 += vals[j] * vals[j];
            #pragma unroll
            for (int off = 16; off; off >>= 1) s2 += __shfl_xor_sync(0xffffffffu, s2, off);

            float mx = 0.f;
            #pragma unroll
            for (int j = 0; j < 8; j++) mx = fmaxf(mx, fabsf(vals[j]));
            #pragma unroll
            for (int off = 16; off; off >>= 1) mx = fmaxf(mx, __shfl_xor_sync(0xffffffffu, mx, off));
            float sc    = 127.0f / mx;
            float scinv = mx / 127.0f;

            int h[8];
            float dsum = 0.f;
            #pragma unroll
            for (int j = 0; j < 8; j++) {
                h[j] = (int)rintf(vals[j] * sc);
                float e = vals[j] - (float)h[j] * scinv;
                dsum += e * e;
            }
            #pragma unroll
            for (int off = 16; off; off >>= 1) dsum += __shfl_xor_sync(0xffffffffu, dsum, off);

            int w0 = (h[0] & 0xFF) | ((h[1] & 0xFF) << 8) | ((h[2] & 0xFF) << 16) | (h[3] << 24);
            int w1 = (h[4] & 0xFF) | ((h[5] & 0xFF) << 8) | ((h[6] & 0xFF) << 16) | (h[7] << 24);
            int* qp = is_code ? g_qe : g_qz;
            qp[(size_t)row * NW + tx]      = w0;
            qp[(size_t)row * NW + 32 + tx] = w1;
            if (tx == 0) {
                float del = sqrtf(dsum);
                if (is_code) {
                    g_enorm2[row] = s2; g_einv[row] = scinv;
                    atomicMax(&g_demaxU, __float_as_uint(del));
                } else {
                    g_znorm2[row] = s2; g_zinv[row] = scinv; g_zdel[row] = del;
                }
            }
        }
    }
    gridbar(gen0 + 1);

    // ================= Phase 2: dp4a screen (group-of-8 mins) ==================
    const int wm = wid >> 1;          // 0..15 -> rows wm*4..+3
    const int wn = wid & 1;           // col half
    const int qbase = blockIdx.x * 64;

    // A load, transposed: [word][row]
    {
        int row = tid >> 4, p = tid & 15;    // 64 rows x 16 threads
        int w = p * 4;
        int4 v = *(const int4*)&g_qz[(size_t)(qbase + row) * NW + w];
        As[(w + 0) * 64 + row] = v.x;
        As[(w + 1) * 64 + row] = v.y;
        As[(w + 2) * 64 + row] = v.z;
        As[(w + 3) * 64 + row] = v.w;
    }

    float z2s[4], qiv[4];
    #pragma unroll
    for (int i = 0; i < 4; i++) {
        int r = qbase + wm * 4 + i;
        z2s[i] = g_znorm2[r];
        qiv[i] = g_zinv[r];
    }

    // B staging: thread -> code c = tid>>2, quarter q = tid&3 (words q*16..+15)
    const int c = tid >> 2;
    const int q = tid & 3;
    int4 br[4];
    #pragma unroll
    for (int j = 0; j < 4; j++)
        br[j] = *(const int4*)&g_qe[(size_t)c * NW + q * 16 + j * 4];

    int acc[4][4];

    #pragma unroll 1
    for (int t = 0; t < NTILE; t++) {
        __syncthreads();    // prior tile's Bs reads complete
        #pragma unroll
        for (int j = 0; j < 4; j++) {
            int w = q * 16 + j * 4;
            Bs[(w + 0) * 256 + c] = br[j].x;
            Bs[(w + 1) * 256 + c] = br[j].y;
            Bs[(w + 2) * 256 + c] = br[j].z;
            Bs[(w + 3) * 256 + c] = br[j].w;
        }
        __syncthreads();
        if (t + 1 < NTILE) {
            #pragma unroll
            for (int j = 0; j < 4; j++)
                br[j] = *(const int4*)&g_qe[(size_t)((t + 1) * 256 + c) * NW + q * 16 + j * 4];
        }

        #pragma unroll
        for (int i = 0; i < 4; i++) {
            acc[i][0] = 0; acc[i][1] = 0; acc[i][2] = 0; acc[i][3] = 0;
        }
        const int* B = Bs + wn * 128;
        #pragma unroll 8
        for (int kw = 0; kw < 64; kw++) {
            int4 a = *(const int4*)&As[kw * 64 + wm * 4];
            int4 b = *(const int4*)&B[kw * 256 + tx * 4];
            acc[0][0] = __dp4a(a.x, b.x, acc[0][0]); acc[0][1] = __dp4a(a.x, b.y, acc[0][1]);
            acc[0][2] = __dp4a(a.x, b.z, acc[0][2]); acc[0][3] = __dp4a(a.x, b.w, acc[0][3]);
            acc[1][0] = __dp4a(a.y, b.x, acc[1][0]); acc[1][1] = __dp4a(a.y, b.y, acc[1][1]);
            acc[1][2] = __dp4a(a.y, b.z, acc[1][2]); acc[1][3] = __dp4a(a.y, b.w, acc[1][3]);
            acc[2][0] = __dp4a(a.z, b.x, acc[2][0]); acc[2][1] = __dp4a(a.z, b.y, acc[2][1]);
            acc[2][2] = __dp4a(a.z, b.z, acc[2][2]); acc[2][3] = __dp4a(a.z, b.w, acc[2][3]);
            acc[3][0] = __dp4a(a.w, b.x, acc[3][0]); acc[3][1] = __dp4a(a.w, b.y, acc[3][1]);
            acc[3][2] = __dp4a(a.w, b.z, acc[3][2]); acc[3][3] = __dp4a(a.w, b.w, acc[3][3]);
        }

        // epilogue: per-row per-8-code fp16 min
        int colb = t * 256 + wn * 128 + tx * 4;
        float4 e2  = *(const float4*)&g_enorm2[colb];
        float4 civ = *(const float4*)&g_einv[colb];
        int g8 = t * 32 + wn * 16 + (tx >> 1);
        #pragma unroll
        for (int i = 0; i < 4; i++) {
            float sc = qiv[i];
            float k0 = z2s[i] + e2.x - 2.0f * ((float)acc[i][0] * (sc * civ.x));
            float k1 = z2s[i] + e2.y - 2.0f * ((float)acc[i][1] * (sc * civ.y));
            float k2 = z2s[i] + e2.z - 2.0f * ((float)acc[i][2] * (sc * civ.z));
            float k3 = z2s[i] + e2.w - 2.0f * ((float)acc[i][3] * (sc * civ.w));
            float m = fminf(fminf(k0, k1), fminf(k2, k3));
            m = fminf(m, __shfl_xor_sync(0xffffffffu, m, 1));
            if ((tx & 1) == 0)
                gmin8[(wm * 4 + i) * 1024 + g8] = __float2half_rn(m);
        }
    }

    // init tail shared state
    if (tid == 0) s_cnt = 0;
    if (tid < 64) s_best[tid] = 0xFFFFFFFFFFFFFFFFull;
    __syncthreads();

    // ---- stage A: per-row lm + threshold (2 rows per warp) ----
    {
        float D = __uint_as_float(g_demaxU);
        #pragma unroll
        for (int k = 0; k < 2; k++) {
            int r = wid * 2 + k;
            float lm = 3.4e38f;
            const __half* gr = &gmin8[r * 1024];
            #pragma unroll
            for (int p = 0; p < 4; p++) {
                uint4 v = *(const uint4*)&gr[p * 256 + tx * 8];
                uint32_t ws[4] = {v.x, v.y, v.z, v.w};
                #pragma unroll
                for (int u = 0; u < 4; u++) {
                    float2 f = __half22float2(*(__half2*)&ws[u]);
                    lm = fminf(lm, fminf(f.x, f.y));
                }
            }
            #pragma unroll
            for (int off = 16; off; off >>= 1) lm = fminf(lm, __shfl_xor_sync(0xffffffffu, lm, off));
            if (tx == 0) {
                float dq = g_zdel[qbase + r];
                float M = 2.0f * (dq + D + dq * D);
                s_thr[r] = lm + 2.0f * M + 4e-3f;    // sound window + fp16 slack
            }
        }
    }
    __syncthreads();

    // ---- stage B: scan + push candidate (row, group8) into list ----
    int* list = As;   // reuse As region: 4096 ints
    {
        #pragma unroll 1
        for (int i = 0; i < 8; i++) {
            int u8 = tid + i * 1024;                 // uint4 index, 8 halfs
            int r = u8 >> 7;                          // (u8*8)>>10
            float thr = s_thr[r];
            uint4 v = *(const uint4*)&gmin8[u8 * 8];
            int gbase = (u8 * 8) & 1023;
            uint32_t ws[4] = {v.x, v.y, v.z, v.w};
            #pragma unroll
            for (int u = 0; u < 4; u++) {
                float2 f = __half22float2(*(__half2*)&ws[u]);
                if (f.x <= thr) { int p = atomicAdd(&s_cnt, 1); if (p < LIST_CAP) list[p] = (r << 16) | (gbase + u * 2); }
                if (f.y <= thr) { int p = atomicAdd(&s_cnt, 1); if (p < LIST_CAP) list[p] = (r << 16) | (gbase + u * 2 + 1); }
            }
        }
    }
    __syncthreads();
    int ncand = s_cnt;

    // ---- stage C: exact rescore (warp per entry; 8 codes per entry) ----
    if (ncand <= LIST_CAP) {
        #pragma unroll 1
        for (int e = wid; e < ncand; e += 32) {
            int ent = list[e];
            int r  = ent >> 16;
            int g8 = ent & 0xFFFF;
            int rowg = qbase + r;
            float z2r = g_znorm2[rowg];
            const float4* zvw = (const float4*)&g_znorm[(size_t)rowg * DIM];
            float4 za = zvw[tx], zb = zvw[tx + 32];
            #pragma unroll 1
            for (int kk = 0; kk < 8; kk++) {
                int code = g8 * 8 + kk;
                const float4* ev = (const float4*)&g_enorm[(size_t)code * DIM];
                float4 ea = ev[tx], eb = ev[tx + 32];
                float d = za.x*ea.x + za.y*ea.y + za.z*ea.z + za.w*ea.w
                        + zb.x*eb.x + zb.y*eb.y + zb.z*eb.z + zb.w*eb.w;
                #pragma unroll
                for (int off = 16; off; off >>= 1) d += __shfl_xor_sync(0xffffffffu, d, off);
                if (tx == 0) {
                    float key = z2r + g_enorm2[code] - 2.0f * d;
                    unsigned long long p =
                        ((unsigned long long)__float_as_uint(key) << 32) | (unsigned)code;
                    atomicMin(&s_best[r], p);
                }
            }
        }
    } else {
        // sound fallback (practically never): re-test every group directly
        #pragma unroll 1
        for (int e = wid; e < 64 * 1024; e += 32) {
            int r  = e >> 10;
            int g8 = e & 1023;
            if (__half2float(gmin8[r * 1024 + g8]) > s_thr[r]) continue;
            int rowg = qbase + r;
            float z2r = g_znorm2[rowg];
            const float4* zvw = (const float4*)&g_znorm[(size_t)rowg * DIM];
            float4 za = zvw[tx], zb = zvw[tx + 32];
            for (int kk = 0; kk < 8; kk++) {
                int code = g8 * 8 + kk;
                const float4* ev = (const float4*)&g_enorm[(size_t)code * DIM];
                float4 ea = ev[tx], eb = ev[tx + 32];
                float d = za.x*ea.x + za.y*ea.y + za.z*ea.z + za.w*ea.w
                        + zb.x*eb.x + zb.y*eb.y + zb.z*eb.z + zb.w*eb.w;
                #pragma unroll
                for (int off = 16; off; off >>= 1) d += __shfl_xor_sync(0xffffffffu, d, off);
                if (tx == 0) {
                    float key = z2r + g_enorm2[code] - 2.0f * d;
                    unsigned long long p =
                        ((unsigned long long)__float_as_uint(key) << 32) | (unsigned)code;
                    atomicMin(&s_best[r], p);
                }
            }
        }
    }
    __syncthreads();

    // ---- stage D: gather + loss partial (2 rows per warp) ----
    {
        #pragma unroll
        for (int k = 0; k < 2; k++) {
            int r = wid * 2 + k;
            int rowg = qbase + r;
            int e = (int)(s_best[r] & 0xFFFFFFFFull) & (NE - 1);
            const float4* evw = (const float4*)&g_enorm[(size_t)e * DIM];
            const float4* zvw = (const float4*)&g_znorm[(size_t)rowg * DIM];
            float4 a0 = evw[tx], a1 = evw[tx + 32];
            float4 b0 = zvw[tx], b1 = zvw[tx + 32];
            if (write_zq) {
                float4* o = (float4*)&zq_out[(size_t)rowg * DIM];
                o[tx]      = a0;
                o[tx + 32] = a1;
            }
            float dx, s = 0.f;
            dx = a0.x - b0.x; s += dx * dx;  dx = a0.y - b0.y; s += dx * dx;
            dx = a0.z - b0.z; s += dx * dx;  dx = a0.w - b0.w; s += dx * dx;
            dx = a1.x - b1.x; s += dx * dx;  dx = a1.y - b1.y; s += dx * dx;
            dx = a1.z - b1.z; s += dx * dx;  dx = a1.w - b1.w; s += dx * dx;
            #pragma unroll
            for (int off = 16; off; off >>= 1) s += __shfl_xor_sync(0xffffffffu, s, off);
            if (tx == 0) {
                g_partial[rowg] = s;
                if (idxf_out) idxf_out[rowg] = (float)e;
            }
        }
    }
    gridbar(gen0 + 2);

    // ================= Phase 3: loss finalize (block 0) ========================
    if (blockIdx.x == 0) {
        float* red = (float*)smem;
        float s = 0.f;
        for (int i = tid; i < NQ; i += NTHR) s += g_partial[i];
        red[tid] = s;
        __syncthreads();
        for (int off = NTHR / 2; off; off >>= 1) {
            if (tid < off) red[tid] += red[tid + off];
            __syncthreads();
        }
        if (tid == 0 && loss_out) loss_out[0] = 1.25f * red[0] / (float)ZQ_ELEMS;
    }
}

// ---------------- launch (no __device__ symbols below!) ----------------
extern "C" void kernel_launch(void* const* d_in, const int* in_sizes, int n_in,
                              void* d_out, int out_size) {
    const float* z  = (const float*)d_in[0];
    const float* ew = (const float*)d_in[1];
    float* out = (float*)d_out;

    int   write_zq = 0;
    float* lossp = nullptr;
    float* idxf  = nullptr;
    if (out_size >= ZQ_ELEMS) {
        write_zq = 1;
        long R = (long)out_size - (long)ZQ_ELEMS;
        if (R >= (long)NQ + 1)      { lossp = out + ZQ_ELEMS; idxf = out + ZQ_ELEMS + 1; }
        else if (R == (long)NQ)     { idxf = out + ZQ_ELEMS; }
        else if (R >= 1)            { lossp = out + ZQ_ELEMS; }
    } else if (out_size == NQ) {
        idxf = out;
    } else if (out_size == 1) {
        lossp = out;
    }

    static int smem_set = 0;
    if (!smem_set) {
        cudaFuncSetAttribute(vq_fused, cudaFuncAttributeMaxDynamicSharedMemorySize, SMEM_SC);
        smem_set = 1;
    }

    vq_fused<<<NBLK, NTHR, SMEM_SC>>>(z, ew, out, idxf, lossp, write_zq);
}